// round 6
// baseline (speedup 1.0000x reference)
#include <cuda_runtime.h>
#include <cstdint>
#include <cuda_fp16.h>
#include <mma.h>

using namespace nvcuda;

// Problem constants
#define BATCH 8
#define SEQ   2048
#define DIM   1024
#define MTOT  (BATCH * SEQ)        // 16384

// GEMM tiling: CTA 128x256, warp 64x64, K-chunk 32, 3-stage cp.async
#define BM 128
#define BN 256
#define BK 32
#define AKP 40                       // A row stride (halves) = 80 B
#define BKP 40                       // B trans row stride
#define BNP 264                      // B non-trans row stride = 528 B
#define A_STAGE 5120                 // 128*40 halves
#define B_STAGE 10240                // max(256*40, 32*264) halves
#define STAGE_HALVES (A_STAGE + B_STAGE)
#define NSTAGE 3
#define SMEM_BYTES (NSTAGE * STAGE_HALVES * 2)   // 92160 B

// Scratch (__device__ globals; allocation-free rule)
__device__ __half g_q[(long long)MTOT * DIM];        // 32 MB
__device__ __half g_k[(long long)MTOT * DIM];        // 32 MB
__device__ __half g_v[(long long)MTOT * DIM];        // 32 MB
__device__ float  g_s[(long long)BATCH * SEQ * SEQ]; // 128 MB (Xh/Wh, then scores/P)

__device__ __forceinline__ void cp16(void* smem, const void* gmem) {
    unsigned s = (unsigned)__cvta_generic_to_shared(smem);
    asm volatile("cp.async.cg.shared.global [%0], [%1], 16;\n" :: "r"(s), "l"(gmem));
}
#define CP_COMMIT() asm volatile("cp.async.commit_group;\n")

// ---------------------------------------------------------------------------
// FP16 WMMA GEMM (fp32 accumulate), 3-stage cp.async, 64x64 warp tiles.
//   C[M,N] = scale * (A[M,K] @ B(^T)) (+ bias, HALF_OUT only)
// ---------------------------------------------------------------------------
template <bool TRANSB, bool HALF_OUT>
__global__ __launch_bounds__(256, 1)
void gemm_fp16(const __half* __restrict__ Ab, const __half* __restrict__ Bb,
               const float* __restrict__ bias, void* __restrict__ Cb,
               int K, int lda, int ldb, int ldc,
               long long sA, long long sB, long long sC, float scale)
{
    extern __shared__ __half sh[];
    __shared__ float epi[8][16 * 20];   // per-warp fp32 staging for half epilogue
    __shared__ float biasS[BN];

    const __half* A = Ab + (long long)blockIdx.z * sA;
    const __half* B = Bb + (long long)blockIdx.z * sB;

    const int m0 = blockIdx.y * BM;
    const int n0 = blockIdx.x * BN;
    const int t  = threadIdx.x;
    const int warp = t >> 5;
    const int lid  = t & 31;
    const int wm = warp >> 2;   // 0..1 (64-row slab)
    const int wn = warp & 3;    // 0..3 (64-col slab)

    if (HALF_OUT) biasS[t] = bias ? bias[n0 + t] : 0.0f;

    wmma::fragment<wmma::accumulator, 16, 16, 16, float> acc[4][4];
    #pragma unroll
    for (int mi = 0; mi < 4; mi++)
        #pragma unroll
        for (int nj = 0; nj < 4; nj++)
            wmma::fill_fragment(acc[mi][nj], 0.0f);

    // Stage one K=32 chunk into stage buffer s3 (0..2)
    auto stage = [&](int chunk, int s3) {
        const int k0 = chunk * BK;
        __half* Ad = sh + s3 * STAGE_HALVES;
        __half* Bd = Ad + A_STAGE;
        #pragma unroll
        for (int j = 0; j < 2; j++) {              // A: 128x32 = 512 cp16
            int idx = t + 256 * j;
            int r  = idx >> 2;
            int c8 = (idx & 3) << 3;
            cp16(&Ad[r * AKP + c8], &A[(long long)(m0 + r) * lda + k0 + c8]);
        }
        if (TRANSB) {
            #pragma unroll
            for (int j = 0; j < 4; j++) {          // B: 256x32 = 1024 cp16
                int idx = t + 256 * j;
                int r  = idx >> 2;
                int c8 = (idx & 3) << 3;
                cp16(&Bd[r * BKP + c8], &B[(long long)(n0 + r) * ldb + k0 + c8]);
            }
        } else {
            #pragma unroll
            for (int j = 0; j < 4; j++) {          // B: 32x256 = 1024 cp16
                int idx = t + 256 * j;
                int r  = idx >> 5;                 // 0..31
                int c8 = (idx & 31) << 3;          // 0..248
                cp16(&Bd[r * BNP + c8], &B[(long long)(k0 + r) * ldb + n0 + c8]);
            }
        }
        CP_COMMIT();
    };

    const int nchunk = K / BK;
    stage(0, 0);
    stage(1, 1);

    int s3 = 0;                 // stage slot for current chunk (i % 3)
    for (int i = 0; i < nchunk; i++) {
        if (i + 1 < nchunk) asm volatile("cp.async.wait_group 1;\n");
        else                asm volatile("cp.async.wait_group 0;\n");
        __syncthreads();

        if (i + 2 < nchunk) {
            int ns = s3 + 2; if (ns >= 3) ns -= 3;
            stage(i + 2, ns);
        }

        const __half* Ac = sh + s3 * STAGE_HALVES;
        const __half* Bc = Ac + A_STAGE;

        #pragma unroll
        for (int kk = 0; kk < BK; kk += 16) {
            wmma::fragment<wmma::matrix_a, 16, 16, 16, __half, wmma::row_major> af[4];
            #pragma unroll
            for (int mi = 0; mi < 4; mi++)
                wmma::load_matrix_sync(af[mi], &Ac[(wm * 64 + mi * 16) * AKP + kk], AKP);

            #pragma unroll
            for (int nj = 0; nj < 4; nj++) {
                if constexpr (TRANSB) {
                    wmma::fragment<wmma::matrix_b, 16, 16, 16, __half,
                                   wmma::col_major> bf;
                    wmma::load_matrix_sync(bf, &Bc[(wn * 64 + nj * 16) * BKP + kk], BKP);
                    #pragma unroll
                    for (int mi = 0; mi < 4; mi++)
                        wmma::mma_sync(acc[mi][nj], af[mi], bf, acc[mi][nj]);
                } else {
                    wmma::fragment<wmma::matrix_b, 16, 16, 16, __half,
                                   wmma::row_major> bf;
                    wmma::load_matrix_sync(bf, &Bc[kk * BNP + wn * 64 + nj * 16], BNP);
                    #pragma unroll
                    for (int mi = 0; mi < 4; mi++)
                        wmma::mma_sync(acc[mi][nj], af[mi], bf, acc[mi][nj]);
                }
            }
        }
        __syncthreads();
        s3 += 1; if (s3 >= 3) s3 -= 3;
    }

    // Epilogue
    if constexpr (!HALF_OUT) {
        float* C = (float*)Cb + (long long)blockIdx.z * sC;
        #pragma unroll
        for (int mi = 0; mi < 4; mi++)
            #pragma unroll
            for (int nj = 0; nj < 4; nj++) {
                if (scale != 1.0f) {
                    #pragma unroll
                    for (int e = 0; e < acc[mi][nj].num_elements; e++)
                        acc[mi][nj].x[e] *= scale;
                }
                wmma::store_matrix_sync(
                    &C[(long long)(m0 + wm * 64 + mi * 16) * ldc + n0 + wn * 64 + nj * 16],
                    acc[mi][nj], ldc, wmma::mem_row_major);
            }
    } else {
        __half* C = (__half*)Cb + (long long)blockIdx.z * sC;
        float* ep = epi[warp];
        const int r  = lid >> 1;          // 0..15
        const int ch = (lid & 1) * 8;     // 0 or 8
        #pragma unroll
        for (int mi = 0; mi < 4; mi++)
            #pragma unroll
            for (int nj = 0; nj < 4; nj++) {
                wmma::store_matrix_sync(ep, acc[mi][nj], 20, wmma::mem_row_major);
                __syncwarp();
                const int colb = wn * 64 + nj * 16 + ch;
                __half h[8];
                #pragma unroll
                for (int i = 0; i < 8; i++)
                    h[i] = __float2half_rn(ep[r * 20 + ch + i] + biasS[colb + i]);
                *(uint4*)&C[(long long)(m0 + wm * 64 + mi * 16 + r) * ldc + n0 + colb] =
                    *(uint4*)h;
                __syncwarp();
            }
    }
}

// ---------------------------------------------------------------------------
// float -> half conversion (8 elems/thread, grid-stride)
// ---------------------------------------------------------------------------
__global__ __launch_bounds__(256)
void cvt_f2h(const float4* __restrict__ in, uint4* __restrict__ out, int n8)
{
    for (int i = blockIdx.x * blockDim.x + threadIdx.x; i < n8;
         i += gridDim.x * blockDim.x) {
        float4 a = in[i * 2], b = in[i * 2 + 1];
        __half h[8];
        h[0] = __float2half_rn(a.x); h[1] = __float2half_rn(a.y);
        h[2] = __float2half_rn(a.z); h[3] = __float2half_rn(a.w);
        h[4] = __float2half_rn(b.x); h[5] = __float2half_rn(b.y);
        h[6] = __float2half_rn(b.z); h[7] = __float2half_rn(b.w);
        out[i] = *(uint4*)h;
    }
}

// ---------------------------------------------------------------------------
// Row softmax over 2048 fp32 scores; writes 2048 halves IN PLACE (row head).
// ---------------------------------------------------------------------------
__global__ __launch_bounds__(256)
void softmax2048(float* __restrict__ S)
{
    float* p = S + (long long)blockIdx.x * SEQ;
    const int t = threadIdx.x;

    float4 v0 = *(const float4*)&p[t * 4];
    float4 v1 = *(const float4*)&p[1024 + t * 4];

    float m = fmaxf(fmaxf(fmaxf(v0.x, v0.y), fmaxf(v0.z, v0.w)),
                    fmaxf(fmaxf(v1.x, v1.y), fmaxf(v1.z, v1.w)));
    #pragma unroll
    for (int o = 16; o > 0; o >>= 1)
        m = fmaxf(m, __shfl_xor_sync(0xffffffffu, m, o));

    __shared__ float sm[8], ss[8];
    if ((t & 31) == 0) sm[t >> 5] = m;
    __syncthreads();
    m = fmaxf(fmaxf(fmaxf(sm[0], sm[1]), fmaxf(sm[2], sm[3])),
              fmaxf(fmaxf(sm[4], sm[5]), fmaxf(sm[6], sm[7])));

    v0.x = __expf(v0.x - m); v0.y = __expf(v0.y - m);
    v0.z = __expf(v0.z - m); v0.w = __expf(v0.w - m);
    v1.x = __expf(v1.x - m); v1.y = __expf(v1.y - m);
    v1.z = __expf(v1.z - m); v1.w = __expf(v1.w - m);

    float s = (v0.x + v0.y + v0.z + v0.w) + (v1.x + v1.y + v1.z + v1.w);
    #pragma unroll
    for (int o = 16; o > 0; o >>= 1)
        s += __shfl_xor_sync(0xffffffffu, s, o);
    if ((t & 31) == 0) ss[t >> 5] = s;
    __syncthreads();
    s = (ss[0] + ss[1] + ss[2] + ss[3]) + (ss[4] + ss[5] + ss[6] + ss[7]);

    float inv = 1.0f / s;
    __half* ph = (__half*)p;
    __half h0[4], h1[4];
    h0[0] = __float2half_rn(v0.x * inv); h0[1] = __float2half_rn(v0.y * inv);
    h0[2] = __float2half_rn(v0.z * inv); h0[3] = __float2half_rn(v0.w * inv);
    h1[0] = __float2half_rn(v1.x * inv); h1[1] = __float2half_rn(v1.y * inv);
    h1[2] = __float2half_rn(v1.z * inv); h1[3] = __float2half_rn(v1.w * inv);
    *(uint2*)&ph[t * 4]        = *(uint2*)h0;
    *(uint2*)&ph[1024 + t * 4] = *(uint2*)h1;
}

// ---------------------------------------------------------------------------
extern "C" void kernel_launch(void* const* d_in, const int* in_sizes, int n_in,
                              void* d_out, int out_size)
{
    const float* X  = (const float*)d_in[0];
    const float* Wq = (const float*)d_in[1];
    const float* bq = (const float*)d_in[2];
    const float* Wk = (const float*)d_in[3];
    const float* bk = (const float*)d_in[4];
    const float* Wv = (const float*)d_in[5];
    const float* bv = (const float*)d_in[6];
    float* out = (float*)d_out;

    __half *q, *k, *v;
    float* s;
    cudaGetSymbolAddress((void**)&q, g_q);
    cudaGetSymbolAddress((void**)&k, g_k);
    cudaGetSymbolAddress((void**)&v, g_v);
    cudaGetSymbolAddress((void**)&s, g_s);

    cudaFuncSetAttribute(gemm_fp16<false, true>,
                         cudaFuncAttributeMaxDynamicSharedMemorySize, SMEM_BYTES);
    cudaFuncSetAttribute(gemm_fp16<true, false>,
                         cudaFuncAttributeMaxDynamicSharedMemorySize, SMEM_BYTES);
    cudaFuncSetAttribute(gemm_fp16<false, false>,
                         cudaFuncAttributeMaxDynamicSharedMemorySize, SMEM_BYTES);

    const long long TD = (long long)SEQ * DIM;   // 2097152
    const long long TT = (long long)SEQ * SEQ;   // 4194304

    // Half scratch living inside g_s until phase 2 overwrites it:
    __half* Xh  = (__half*)s;                                  // 16M halves
    __half* Wqh = (__half*)(s + (long long)MTOT * DIM / 2);    // +1M halves each
    __half* Wkh = Wqh + (long long)DIM * DIM;
    __half* Wvh = Wkh + (long long)DIM * DIM;

    // Phase 0: convert inputs to half
    cvt_f2h<<<2048, 256>>>((const float4*)X,  (uint4*)Xh,  MTOT * DIM / 8);
    cvt_f2h<<<512, 256>>>((const float4*)Wq, (uint4*)Wqh, DIM * DIM / 8);
    cvt_f2h<<<512, 256>>>((const float4*)Wk, (uint4*)Wkh, DIM * DIM / 8);
    cvt_f2h<<<512, 256>>>((const float4*)Wv, (uint4*)Wvh, DIM * DIM / 8);

    // Phase 1: projections -> half Q/K/V
    {
        dim3 grid(DIM / BN, MTOT / BM, 1);  // (4, 128)
        gemm_fp16<false, true><<<grid, 256, SMEM_BYTES>>>(
            Xh, Wqh, bq, q, DIM, DIM, DIM, DIM, 0, 0, 0, 1.0f);
        gemm_fp16<false, true><<<grid, 256, SMEM_BYTES>>>(
            Xh, Wkh, bk, k, DIM, DIM, DIM, DIM, 0, 0, 0, 1.0f);
        gemm_fp16<false, true><<<grid, 256, SMEM_BYTES>>>(
            Xh, Wvh, bv, v, DIM, DIM, DIM, DIM, 0, 0, 0, 1.0f);
    }

    // Phase 2: scores = (Q @ K^T) / 32  (fp32, overwrites Xh/Wh region)
    {
        dim3 grid(SEQ / BN, SEQ / BM, BATCH);  // (8, 16, 8)
        gemm_fp16<true, false><<<grid, 256, SMEM_BYTES>>>(
            q, k, nullptr, s, DIM, DIM, DIM, SEQ, TD, TD, TT, 0.03125f);
    }

    // Phase 3: softmax; P written as half in place (row stride 2*SEQ halves)
    softmax2048<<<MTOT, 256>>>(s);

    // Phase 4: out = P @ V  (A = half P with lda = 2*SEQ halves)
    {
        dim3 grid(DIM / BN, SEQ / BM, BATCH);  // (4, 16, 8)
        gemm_fp16<false, false><<<grid, 256, SMEM_BYTES>>>(
            (const __half*)s, v, nullptr, out, SEQ, 2 * SEQ, DIM, DIM,
            2 * TT, TD, TD, 1.0f);
    }
}

// round 7
// speedup vs baseline: 1.2803x; 1.2803x over previous
#include <cuda_runtime.h>
#include <cstdint>
#include <cuda_fp16.h>
#include <mma.h>

using namespace nvcuda;

// Problem constants
#define BATCH 8
#define SEQ   2048
#define DIM   1024
#define MTOT  (BATCH * SEQ)        // 16384

// GEMM tiling: CTA 128x128, warp 64x32, K-chunk 32, 3-stage cp.async
#define BM 128
#define BN 128
#define BK 32
#define AKP 40                       // A row stride (halves) = 80 B
#define BKP 40                       // B trans row stride
#define BNP 136                      // B non-trans row stride = 272 B
#define A_STAGE 5120                 // 128*40 halves
#define B_STAGE 5120                 // max(128*40, 32*136) halves
#define STAGE_HALVES (A_STAGE + B_STAGE)
#define NSTAGE 3
#define SMEM_BYTES (NSTAGE * STAGE_HALVES * 2)   // 61440 B

// Scratch (__device__ globals; allocation-free rule)
__device__ __half g_q[(long long)MTOT * DIM];        // 32 MB
__device__ __half g_k[(long long)MTOT * DIM];        // 32 MB
__device__ __half g_v[(long long)MTOT * DIM];        // 32 MB
__device__ float  g_s[(long long)BATCH * SEQ * SEQ]; // 128 MB (Xh/Wh, then scores/P)

__device__ __forceinline__ void cp16(void* smem, const void* gmem) {
    unsigned s = (unsigned)__cvta_generic_to_shared(smem);
    asm volatile("cp.async.cg.shared.global [%0], [%1], 16;\n" :: "r"(s), "l"(gmem));
}
#define CP_COMMIT() asm volatile("cp.async.commit_group;\n")

// ---------------------------------------------------------------------------
// FP16 WMMA GEMM (fp32 accumulate), 3-stage cp.async, 64x32 warp tiles.
//   C[M,N] = scale * (A[M,K] @ B(^T)) (+ bias, HALF_OUT only)
//   QKV3: blockIdx.z selects (B,bias,C) from {0:args, 1:B1/bias1/C1, 2:B2/...};
//         A shared across z. Otherwise blockIdx.z is a batch index via sB/sC.
// ---------------------------------------------------------------------------
template <bool TRANSB, bool HALF_OUT, bool QKV3>
__global__ __launch_bounds__(256, 2)
void gemm_fp16(const __half* __restrict__ Ab, const __half* __restrict__ Bb,
               const float* __restrict__ bias, void* __restrict__ Cb,
               int K, int lda, int ldb, int ldc,
               long long sA, long long sB, long long sC, float scale,
               const __half* __restrict__ Bb1 = nullptr,
               const __half* __restrict__ Bb2 = nullptr,
               const float* __restrict__ bias1 = nullptr,
               const float* __restrict__ bias2 = nullptr,
               void* __restrict__ Cb1 = nullptr,
               void* __restrict__ Cb2 = nullptr)
{
    extern __shared__ __half sh[];
    __shared__ float epi[8][16 * 20];   // per-warp fp32 staging for half epilogue
    __shared__ float biasS[BN];

    const __half* A = Ab;
    const __half* B = Bb;
    const float*  bi = bias;
    void*         Cv = Cb;

    if constexpr (QKV3) {
        if (blockIdx.z == 1)      { B = Bb1; bi = bias1; Cv = Cb1; }
        else if (blockIdx.z == 2) { B = Bb2; bi = bias2; Cv = Cb2; }
    } else {
        A += (long long)blockIdx.z * sA;
        B += (long long)blockIdx.z * sB;
    }

    const int m0 = blockIdx.y * BM;
    const int n0 = blockIdx.x * BN;
    const int t  = threadIdx.x;
    const int warp = t >> 5;
    const int lid  = t & 31;
    const int wm = warp >> 2;   // 0..1 (64-row slab)
    const int wn = warp & 3;    // 0..3 (32-col slab)

    if (HALF_OUT && t < BN) biasS[t] = bi ? bi[n0 + t] : 0.0f;

    wmma::fragment<wmma::accumulator, 16, 16, 16, float> acc[4][2];
    #pragma unroll
    for (int mi = 0; mi < 4; mi++)
        #pragma unroll
        for (int nj = 0; nj < 2; nj++)
            wmma::fill_fragment(acc[mi][nj], 0.0f);

    // Stage one K=32 chunk into stage slot st (0..2)
    auto stage = [&](int chunk, int st) {
        const int k0 = chunk * BK;
        __half* Ad = sh + st * STAGE_HALVES;
        __half* Bd = Ad + A_STAGE;
        #pragma unroll
        for (int j = 0; j < 2; j++) {              // A: 128x32 = 512 cp16
            int idx = t + 256 * j;
            int r  = idx >> 2;
            int c8 = (idx & 3) << 3;
            cp16(&Ad[r * AKP + c8], &A[(long long)(m0 + r) * lda + k0 + c8]);
        }
        if (TRANSB) {
            #pragma unroll
            for (int j = 0; j < 2; j++) {          // B: 128x32 = 512 cp16
                int idx = t + 256 * j;
                int r  = idx >> 2;
                int c8 = (idx & 3) << 3;
                cp16(&Bd[r * BKP + c8], &B[(long long)(n0 + r) * ldb + k0 + c8]);
            }
        } else {
            #pragma unroll
            for (int j = 0; j < 2; j++) {          // B: 32x128 = 512 cp16
                int idx = t + 256 * j;
                int r  = idx >> 4;                 // 0..31
                int c8 = (idx & 15) << 3;          // 0..120
                cp16(&Bd[r * BNP + c8], &B[(long long)(k0 + r) * ldb + n0 + c8]);
            }
        }
        CP_COMMIT();
    };

    const int nchunk = K / BK;
    stage(0, 0);
    stage(1, 1);

    int st = 0;
    for (int i = 0; i < nchunk; i++) {
        if (i + 1 < nchunk) asm volatile("cp.async.wait_group 1;\n");
        else                asm volatile("cp.async.wait_group 0;\n");
        __syncthreads();

        if (i + 2 < nchunk) {
            int ns = st + 2; if (ns >= 3) ns -= 3;
            stage(i + 2, ns);
        }

        const __half* Ac = sh + st * STAGE_HALVES;
        const __half* Bc = Ac + A_STAGE;

        #pragma unroll
        for (int kk = 0; kk < BK; kk += 16) {
            wmma::fragment<wmma::matrix_a, 16, 16, 16, __half, wmma::row_major> af[4];
            #pragma unroll
            for (int mi = 0; mi < 4; mi++)
                wmma::load_matrix_sync(af[mi], &Ac[(wm * 64 + mi * 16) * AKP + kk], AKP);

            #pragma unroll
            for (int nj = 0; nj < 2; nj++) {
                if constexpr (TRANSB) {
                    wmma::fragment<wmma::matrix_b, 16, 16, 16, __half,
                                   wmma::col_major> bf;
                    wmma::load_matrix_sync(bf, &Bc[(wn * 32 + nj * 16) * BKP + kk], BKP);
                    #pragma unroll
                    for (int mi = 0; mi < 4; mi++)
                        wmma::mma_sync(acc[mi][nj], af[mi], bf, acc[mi][nj]);
                } else {
                    wmma::fragment<wmma::matrix_b, 16, 16, 16, __half,
                                   wmma::row_major> bf;
                    wmma::load_matrix_sync(bf, &Bc[kk * BNP + wn * 32 + nj * 16], BNP);
                    #pragma unroll
                    for (int mi = 0; mi < 4; mi++)
                        wmma::mma_sync(acc[mi][nj], af[mi], bf, acc[mi][nj]);
                }
            }
        }
        __syncthreads();
        st += 1; if (st >= 3) st -= 3;
    }

    // Epilogue
    if constexpr (!HALF_OUT) {
        float* C = (float*)Cv + (QKV3 ? 0LL : (long long)blockIdx.z * sC);
        #pragma unroll
        for (int mi = 0; mi < 4; mi++)
            #pragma unroll
            for (int nj = 0; nj < 2; nj++) {
                if (scale != 1.0f) {
                    #pragma unroll
                    for (int e = 0; e < acc[mi][nj].num_elements; e++)
                        acc[mi][nj].x[e] *= scale;
                }
                wmma::store_matrix_sync(
                    &C[(long long)(m0 + wm * 64 + mi * 16) * ldc + n0 + wn * 32 + nj * 16],
                    acc[mi][nj], ldc, wmma::mem_row_major);
            }
    } else {
        __half* C = (__half*)Cv + (QKV3 ? 0LL : (long long)blockIdx.z * sC);
        float* ep = epi[warp];
        const int r  = lid >> 1;          // 0..15
        const int ch = (lid & 1) * 8;     // 0 or 8
        #pragma unroll
        for (int mi = 0; mi < 4; mi++)
            #pragma unroll
            for (int nj = 0; nj < 2; nj++) {
                wmma::store_matrix_sync(ep, acc[mi][nj], 20, wmma::mem_row_major);
                __syncwarp();
                const int colb = wn * 32 + nj * 16 + ch;
                __half h[8];
                #pragma unroll
                for (int i = 0; i < 8; i++)
                    h[i] = __float2half_rn(ep[r * 20 + ch + i] + biasS[colb + i]);
                *(uint4*)&C[(long long)(m0 + wm * 64 + mi * 16 + r) * ldc + n0 + colb] =
                    *(uint4*)h;
                __syncwarp();
            }
    }
}

// ---------------------------------------------------------------------------
// float -> half conversion (8 elems/thread, grid-stride)
// ---------------------------------------------------------------------------
__global__ __launch_bounds__(256)
void cvt_f2h(const float4* __restrict__ in, uint4* __restrict__ out, int n8)
{
    for (int i = blockIdx.x * blockDim.x + threadIdx.x; i < n8;
         i += gridDim.x * blockDim.x) {
        float4 a = in[i * 2], b = in[i * 2 + 1];
        __half h[8];
        h[0] = __float2half_rn(a.x); h[1] = __float2half_rn(a.y);
        h[2] = __float2half_rn(a.z); h[3] = __float2half_rn(a.w);
        h[4] = __float2half_rn(b.x); h[5] = __float2half_rn(b.y);
        h[6] = __float2half_rn(b.z); h[7] = __float2half_rn(b.w);
        out[i] = *(uint4*)h;
    }
}

// ---------------------------------------------------------------------------
// Row softmax over 2048 fp32 scores; writes 2048 halves IN PLACE (row head).
// ---------------------------------------------------------------------------
__global__ __launch_bounds__(256)
void softmax2048(float* __restrict__ S)
{
    float* p = S + (long long)blockIdx.x * SEQ;
    const int t = threadIdx.x;

    float4 v0 = *(const float4*)&p[t * 4];
    float4 v1 = *(const float4*)&p[1024 + t * 4];

    float m = fmaxf(fmaxf(fmaxf(v0.x, v0.y), fmaxf(v0.z, v0.w)),
                    fmaxf(fmaxf(v1.x, v1.y), fmaxf(v1.z, v1.w)));
    #pragma unroll
    for (int o = 16; o > 0; o >>= 1)
        m = fmaxf(m, __shfl_xor_sync(0xffffffffu, m, o));

    __shared__ float sm[8], ss[8];
    if ((t & 31) == 0) sm[t >> 5] = m;
    __syncthreads();
    m = fmaxf(fmaxf(fmaxf(sm[0], sm[1]), fmaxf(sm[2], sm[3])),
              fmaxf(fmaxf(sm[4], sm[5]), fmaxf(sm[6], sm[7])));

    v0.x = __expf(v0.x - m); v0.y = __expf(v0.y - m);
    v0.z = __expf(v0.z - m); v0.w = __expf(v0.w - m);
    v1.x = __expf(v1.x - m); v1.y = __expf(v1.y - m);
    v1.z = __expf(v1.z - m); v1.w = __expf(v1.w - m);

    float s = (v0.x + v0.y + v0.z + v0.w) + (v1.x + v1.y + v1.z + v1.w);
    #pragma unroll
    for (int o = 16; o > 0; o >>= 1)
        s += __shfl_xor_sync(0xffffffffu, s, o);
    if ((t & 31) == 0) ss[t >> 5] = s;
    __syncthreads();
    s = (ss[0] + ss[1] + ss[2] + ss[3]) + (ss[4] + ss[5] + ss[6] + ss[7]);

    float inv = 1.0f / s;
    __half* ph = (__half*)p;
    __half h0[4], h1[4];
    h0[0] = __float2half_rn(v0.x * inv); h0[1] = __float2half_rn(v0.y * inv);
    h0[2] = __float2half_rn(v0.z * inv); h0[3] = __float2half_rn(v0.w * inv);
    h1[0] = __float2half_rn(v1.x * inv); h1[1] = __float2half_rn(v1.y * inv);
    h1[2] = __float2half_rn(v1.z * inv); h1[3] = __float2half_rn(v1.w * inv);
    *(uint2*)&ph[t * 4]        = *(uint2*)h0;
    *(uint2*)&ph[1024 + t * 4] = *(uint2*)h1;
}

// ---------------------------------------------------------------------------
extern "C" void kernel_launch(void* const* d_in, const int* in_sizes, int n_in,
                              void* d_out, int out_size)
{
    const float* X  = (const float*)d_in[0];
    const float* Wq = (const float*)d_in[1];
    const float* bq = (const float*)d_in[2];
    const float* Wk = (const float*)d_in[3];
    const float* bk = (const float*)d_in[4];
    const float* Wv = (const float*)d_in[5];
    const float* bv = (const float*)d_in[6];
    float* out = (float*)d_out;

    __half *q, *k, *v;
    float* s;
    cudaGetSymbolAddress((void**)&q, g_q);
    cudaGetSymbolAddress((void**)&k, g_k);
    cudaGetSymbolAddress((void**)&v, g_v);
    cudaGetSymbolAddress((void**)&s, g_s);

    cudaFuncSetAttribute(gemm_fp16<false, true, true>,
                         cudaFuncAttributeMaxDynamicSharedMemorySize, SMEM_BYTES);
    cudaFuncSetAttribute(gemm_fp16<true, false, false>,
                         cudaFuncAttributeMaxDynamicSharedMemorySize, SMEM_BYTES);
    cudaFuncSetAttribute(gemm_fp16<false, false, false>,
                         cudaFuncAttributeMaxDynamicSharedMemorySize, SMEM_BYTES);

    const long long TD = (long long)SEQ * DIM;   // 2097152
    const long long TT = (long long)SEQ * SEQ;   // 4194304

    // Half scratch living inside g_s until phase 2 overwrites it:
    __half* Xh  = (__half*)s;                                  // 16M halves
    __half* Wqh = (__half*)(s + (long long)MTOT * DIM / 2);    // +1M halves each
    __half* Wkh = Wqh + (long long)DIM * DIM;
    __half* Wvh = Wkh + (long long)DIM * DIM;

    // Phase 0: convert inputs to half
    cvt_f2h<<<2048, 256>>>((const float4*)X,  (uint4*)Xh,  MTOT * DIM / 8);
    cvt_f2h<<<512, 256>>>((const float4*)Wq, (uint4*)Wqh, DIM * DIM / 8);
    cvt_f2h<<<512, 256>>>((const float4*)Wk, (uint4*)Wkh, DIM * DIM / 8);
    cvt_f2h<<<512, 256>>>((const float4*)Wv, (uint4*)Wvh, DIM * DIM / 8);

    // Phase 1: fused Q/K/V projections in ONE launch (z selects W/bias/out)
    {
        dim3 grid(DIM / BN, MTOT / BM, 3);  // (8, 128, 3)
        gemm_fp16<false, true, true><<<grid, 256, SMEM_BYTES>>>(
            Xh, Wqh, bq, q, DIM, DIM, DIM, DIM, 0, 0, 0, 1.0f,
            Wkh, Wvh, bk, bv, k, v);
    }

    // Phase 2: scores = (Q @ K^T) / 32  (fp32, overwrites Xh/Wh region)
    {
        dim3 grid(SEQ / BN, SEQ / BM, BATCH);  // (16, 16, 8)
        gemm_fp16<true, false, false><<<grid, 256, SMEM_BYTES>>>(
            q, k, nullptr, s, DIM, DIM, DIM, SEQ, TD, TD, TT, 0.03125f);
    }

    // Phase 3: softmax; P written as half in place (row stride 2*SEQ halves)
    softmax2048<<<MTOT, 256>>>(s);

    // Phase 4: out = P @ V  (A = half P with lda = 2*SEQ halves)
    {
        dim3 grid(DIM / BN, SEQ / BM, BATCH);  // (8, 16, 8)
        gemm_fp16<false, false, false><<<grid, 256, SMEM_BYTES>>>(
            (const __half*)s, v, nullptr, out, SEQ, 2 * SEQ, DIM, DIM,
            2 * TT, TD, TD, 1.0f);
    }
}

// round 8
// speedup vs baseline: 1.3209x; 1.0317x over previous
#include <cuda_runtime.h>
#include <cstdint>
#include <cuda_fp16.h>
#include <mma.h>

using namespace nvcuda;

// Problem constants
#define BATCH 8
#define SEQ   2048
#define DIM   1024
#define MTOT  (BATCH * SEQ)        // 16384

// GEMM tiling: CTA 128x128, warp 64x32, K-chunk 64, double-buffered cp.async
#define BM 128
#define BN 128
#define BK 64
#define AKP 72                       // A row stride (halves) = 144 B
#define BKP 72                       // B trans row stride
#define BNP 136                      // B non-trans row stride = 272 B
#define A_STAGE 9216                 // 128*72 halves
#define B_STAGE 9216                 // max(128*72, 64*136) halves
#define STAGE_HALVES (A_STAGE + B_STAGE)
#define SMEM_BYTES (2 * STAGE_HALVES * 2)   // 73728 B

// Scratch (__device__ globals; allocation-free rule)
__device__ __half g_q[(long long)MTOT * DIM];        // 32 MB
__device__ __half g_k[(long long)MTOT * DIM];        // 32 MB
__device__ __half g_v[(long long)MTOT * DIM];        // 32 MB
__device__ float  g_s[(long long)BATCH * SEQ * SEQ]; // 128 MB (Xh/Wh, then half scores)

__device__ __forceinline__ void cp16(void* smem, const void* gmem) {
    unsigned s = (unsigned)__cvta_generic_to_shared(smem);
    asm volatile("cp.async.cg.shared.global [%0], [%1], 16;\n" :: "r"(s), "l"(gmem));
}
#define CP_COMMIT() asm volatile("cp.async.commit_group;\n")

// ---------------------------------------------------------------------------
// FP16 WMMA GEMM (fp32 accumulate), double-buffered cp.async, 64x32 warp tiles.
//   C[M,N] = scale * (A[M,K] @ B(^T)) (+ bias, HALF_OUT only)
//   QKV3: blockIdx.z in {0,1,2} selects (B, bias, C); A shared across z.
// ---------------------------------------------------------------------------
template <bool TRANSB, bool HALF_OUT, bool QKV3>
__global__ __launch_bounds__(256, 2)
void gemm_fp16(const __half* __restrict__ Ab, const __half* __restrict__ Bb,
               const float* __restrict__ bias, void* __restrict__ Cb,
               int K, int lda, int ldb, int ldc,
               long long sA, long long sB, long long sC, float scale,
               const __half* __restrict__ Bb1 = nullptr,
               const __half* __restrict__ Bb2 = nullptr,
               const float* __restrict__ bias1 = nullptr,
               const float* __restrict__ bias2 = nullptr,
               void* __restrict__ Cb1 = nullptr,
               void* __restrict__ Cb2 = nullptr)
{
    extern __shared__ __half sh[];
    __shared__ float epi[8][16 * 20];
    __shared__ float biasS[BN];

    const __half* A = Ab;
    const __half* B = Bb;
    const float*  bi = bias;
    void*         Cv = Cb;

    if constexpr (QKV3) {
        if (blockIdx.z == 1)      { B = Bb1; bi = bias1; Cv = Cb1; }
        else if (blockIdx.z == 2) { B = Bb2; bi = bias2; Cv = Cb2; }
    } else {
        A += (long long)blockIdx.z * sA;
        B += (long long)blockIdx.z * sB;
    }

    const int m0 = blockIdx.y * BM;
    const int n0 = blockIdx.x * BN;
    const int t  = threadIdx.x;
    const int warp = t >> 5;
    const int lid  = t & 31;
    const int wm = warp >> 2;   // 0..1 (64-row slab)
    const int wn = warp & 3;    // 0..3 (32-col slab)

    if (HALF_OUT && t < BN) biasS[t] = bi ? bi[n0 + t] : 0.0f;

    wmma::fragment<wmma::accumulator, 16, 16, 16, float> acc[4][2];
    #pragma unroll
    for (int mi = 0; mi < 4; mi++)
        #pragma unroll
        for (int nj = 0; nj < 2; nj++)
            wmma::fill_fragment(acc[mi][nj], 0.0f);

    // Stage one K=64 chunk into buffer slot b (0/1)
    auto stage = [&](int chunk, int b) {
        const int k0 = chunk * BK;
        __half* Ad = sh + b * STAGE_HALVES;
        __half* Bd = Ad + A_STAGE;
        #pragma unroll
        for (int j = 0; j < 4; j++) {              // A: 128x64 = 1024 cp16
            int idx = t + 256 * j;
            int r  = idx >> 3;                     // 0..127
            int c8 = (idx & 7) << 3;               // 0..56
            cp16(&Ad[r * AKP + c8], &A[(long long)(m0 + r) * lda + k0 + c8]);
        }
        if (TRANSB) {
            #pragma unroll
            for (int j = 0; j < 4; j++) {          // B: 128x64 = 1024 cp16
                int idx = t + 256 * j;
                int r  = idx >> 3;
                int c8 = (idx & 7) << 3;
                cp16(&Bd[r * BKP + c8], &B[(long long)(n0 + r) * ldb + k0 + c8]);
            }
        } else {
            #pragma unroll
            for (int j = 0; j < 4; j++) {          // B: 64x128 = 1024 cp16
                int idx = t + 256 * j;
                int r  = idx >> 4;                 // 0..63
                int c8 = (idx & 15) << 3;          // 0..120
                cp16(&Bd[r * BNP + c8], &B[(long long)(k0 + r) * ldb + n0 + c8]);
            }
        }
        CP_COMMIT();
    };

    const int nchunk = K / BK;
    stage(0, 0);

    int cur = 0;
    for (int i = 0; i < nchunk; i++) {
        if (i + 1 < nchunk) {
            stage(i + 1, cur ^ 1);
            asm volatile("cp.async.wait_group 1;\n");
        } else {
            asm volatile("cp.async.wait_group 0;\n");
        }
        __syncthreads();

        const __half* Ac = sh + cur * STAGE_HALVES;
        const __half* Bc = Ac + A_STAGE;

        #pragma unroll
        for (int kk = 0; kk < BK; kk += 16) {
            wmma::fragment<wmma::matrix_a, 16, 16, 16, __half, wmma::row_major> af[4];
            #pragma unroll
            for (int mi = 0; mi < 4; mi++)
                wmma::load_matrix_sync(af[mi], &Ac[(wm * 64 + mi * 16) * AKP + kk], AKP);

            #pragma unroll
            for (int nj = 0; nj < 2; nj++) {
                if constexpr (TRANSB) {
                    wmma::fragment<wmma::matrix_b, 16, 16, 16, __half,
                                   wmma::col_major> bf;
                    wmma::load_matrix_sync(bf, &Bc[(wn * 32 + nj * 16) * BKP + kk], BKP);
                    #pragma unroll
                    for (int mi = 0; mi < 4; mi++)
                        wmma::mma_sync(acc[mi][nj], af[mi], bf, acc[mi][nj]);
                } else {
                    wmma::fragment<wmma::matrix_b, 16, 16, 16, __half,
                                   wmma::row_major> bf;
                    wmma::load_matrix_sync(bf, &Bc[kk * BNP + wn * 32 + nj * 16], BNP);
                    #pragma unroll
                    for (int mi = 0; mi < 4; mi++)
                        wmma::mma_sync(acc[mi][nj], af[mi], bf, acc[mi][nj]);
                }
            }
        }
        __syncthreads();
        cur ^= 1;
    }

    // Epilogue
    if constexpr (!HALF_OUT) {
        float* C = (float*)Cv + (QKV3 ? 0LL : (long long)blockIdx.z * sC);
        #pragma unroll
        for (int mi = 0; mi < 4; mi++)
            #pragma unroll
            for (int nj = 0; nj < 2; nj++) {
                if (scale != 1.0f) {
                    #pragma unroll
                    for (int e = 0; e < acc[mi][nj].num_elements; e++)
                        acc[mi][nj].x[e] *= scale;
                }
                wmma::store_matrix_sync(
                    &C[(long long)(m0 + wm * 64 + mi * 16) * ldc + n0 + wn * 32 + nj * 16],
                    acc[mi][nj], ldc, wmma::mem_row_major);
            }
    } else {
        __half* C = (__half*)Cv + (QKV3 ? 0LL : (long long)blockIdx.z * sC);
        float* ep = epi[warp];
        const int r  = lid >> 1;          // 0..15
        const int ch = (lid & 1) * 8;     // 0 or 8
        #pragma unroll
        for (int mi = 0; mi < 4; mi++)
            #pragma unroll
            for (int nj = 0; nj < 2; nj++) {
                wmma::store_matrix_sync(ep, acc[mi][nj], 20, wmma::mem_row_major);
                __syncwarp();
                const int colb = wn * 32 + nj * 16 + ch;
                __half h[8];
                #pragma unroll
                for (int i = 0; i < 8; i++)
                    h[i] = __float2half_rn(ep[r * 20 + ch + i] * scale + biasS[colb + i]);
                *(uint4*)&C[(long long)(m0 + wm * 64 + mi * 16 + r) * ldc + n0 + colb] =
                    *(uint4*)h;
                __syncwarp();
            }
    }
}

// ---------------------------------------------------------------------------
// float -> half conversion (8 elems/thread, grid-stride)
// ---------------------------------------------------------------------------
__global__ __launch_bounds__(256)
void cvt_f2h(const float4* __restrict__ in, uint4* __restrict__ out, int n8)
{
    for (int i = blockIdx.x * blockDim.x + threadIdx.x; i < n8;
         i += gridDim.x * blockDim.x) {
        float4 a = in[i * 2], b = in[i * 2 + 1];
        __half h[8];
        h[0] = __float2half_rn(a.x); h[1] = __float2half_rn(a.y);
        h[2] = __float2half_rn(a.z); h[3] = __float2half_rn(a.w);
        h[4] = __float2half_rn(b.x); h[5] = __float2half_rn(b.y);
        h[6] = __float2half_rn(b.z); h[7] = __float2half_rn(b.w);
        out[i] = *(uint4*)h;
    }
}

// ---------------------------------------------------------------------------
// Row softmax over 2048 HALF scores, fp32 math, writes half in place.
// One block (256 threads) per row; 8 halves per thread.
// ---------------------------------------------------------------------------
__global__ __launch_bounds__(256)
void softmax2048h(__half* __restrict__ S)
{
    __half* p = S + (long long)blockIdx.x * SEQ;
    const int t = threadIdx.x;

    uint4 raw = *(const uint4*)&p[t * 8];
    __half* hp = (__half*)&raw;
    float x[8];
    #pragma unroll
    for (int i = 0; i < 8; i++) x[i] = __half2float(hp[i]);

    float m = x[0];
    #pragma unroll
    for (int i = 1; i < 8; i++) m = fmaxf(m, x[i]);
    #pragma unroll
    for (int o = 16; o > 0; o >>= 1)
        m = fmaxf(m, __shfl_xor_sync(0xffffffffu, m, o));

    __shared__ float sm[8], ss[8];
    if ((t & 31) == 0) sm[t >> 5] = m;
    __syncthreads();
    m = fmaxf(fmaxf(fmaxf(sm[0], sm[1]), fmaxf(sm[2], sm[3])),
              fmaxf(fmaxf(sm[4], sm[5]), fmaxf(sm[6], sm[7])));

    float s = 0.0f;
    #pragma unroll
    for (int i = 0; i < 8; i++) { x[i] = __expf(x[i] - m); s += x[i]; }
    #pragma unroll
    for (int o = 16; o > 0; o >>= 1)
        s += __shfl_xor_sync(0xffffffffu, s, o);
    if ((t & 31) == 0) ss[t >> 5] = s;
    __syncthreads();
    s = (ss[0] + ss[1] + ss[2] + ss[3]) + (ss[4] + ss[5] + ss[6] + ss[7]);

    float inv = 1.0f / s;
    #pragma unroll
    for (int i = 0; i < 8; i++) hp[i] = __float2half_rn(x[i] * inv);
    *(uint4*)&p[t * 8] = raw;
}

// ---------------------------------------------------------------------------
extern "C" void kernel_launch(void* const* d_in, const int* in_sizes, int n_in,
                              void* d_out, int out_size)
{
    const float* X  = (const float*)d_in[0];
    const float* Wq = (const float*)d_in[1];
    const float* bq = (const float*)d_in[2];
    const float* Wk = (const float*)d_in[3];
    const float* bk = (const float*)d_in[4];
    const float* Wv = (const float*)d_in[5];
    const float* bv = (const float*)d_in[6];
    float* out = (float*)d_out;

    __half *q, *k, *v;
    float* s;
    cudaGetSymbolAddress((void**)&q, g_q);
    cudaGetSymbolAddress((void**)&k, g_k);
    cudaGetSymbolAddress((void**)&v, g_v);
    cudaGetSymbolAddress((void**)&s, g_s);

    cudaFuncSetAttribute(gemm_fp16<false, true, true>,
                         cudaFuncAttributeMaxDynamicSharedMemorySize, SMEM_BYTES);
    cudaFuncSetAttribute(gemm_fp16<true, true, false>,
                         cudaFuncAttributeMaxDynamicSharedMemorySize, SMEM_BYTES);
    cudaFuncSetAttribute(gemm_fp16<false, false, false>,
                         cudaFuncAttributeMaxDynamicSharedMemorySize, SMEM_BYTES);

    const long long TD = (long long)SEQ * DIM;   // 2097152
    const long long TT = (long long)SEQ * SEQ;   // 4194304

    // Half scratch inside g_s until phase 2 overwrites it with half scores:
    __half* Xh  = (__half*)s;                                  // 16M halves
    __half* Wqh = (__half*)(s + (long long)MTOT * DIM / 2);
    __half* Wkh = Wqh + (long long)DIM * DIM;
    __half* Wvh = Wkh + (long long)DIM * DIM;
    __half* Sh  = (__half*)s;                                  // scores/P (64 MB)

    // Phase 0: convert inputs to half
    cvt_f2h<<<2048, 256>>>((const float4*)X,  (uint4*)Xh,  MTOT * DIM / 8);
    cvt_f2h<<<512, 256>>>((const float4*)Wq, (uint4*)Wqh, DIM * DIM / 8);
    cvt_f2h<<<512, 256>>>((const float4*)Wk, (uint4*)Wkh, DIM * DIM / 8);
    cvt_f2h<<<512, 256>>>((const float4*)Wv, (uint4*)Wvh, DIM * DIM / 8);

    // Phase 1: fused Q/K/V projections (z selects W/bias/out)
    {
        dim3 grid(DIM / BN, MTOT / BM, 3);  // (8, 128, 3)
        gemm_fp16<false, true, true><<<grid, 256, SMEM_BYTES>>>(
            Xh, Wqh, bq, q, DIM, DIM, DIM, DIM, 0, 0, 0, 1.0f,
            Wkh, Wvh, bk, bv, k, v);
    }

    // Phase 2: scores = (Q @ K^T) / 32, written as HALF
    {
        dim3 grid(SEQ / BN, SEQ / BM, BATCH);  // (16, 16, 8)
        gemm_fp16<true, true, false><<<grid, 256, SMEM_BYTES>>>(
            q, k, nullptr, Sh, DIM, DIM, DIM, SEQ, TD, TD, TT, 0.03125f);
    }

    // Phase 3: softmax on half scores, in place
    softmax2048h<<<MTOT, 256>>>(Sh);

    // Phase 4: out = P @ V (A = half P, contiguous lda = SEQ)
    {
        dim3 grid(DIM / BN, SEQ / BM, BATCH);  // (8, 16, 8)
        gemm_fp16<false, false, false><<<grid, 256, SMEM_BYTES>>>(
            Sh, v, nullptr, out, SEQ, SEQ, DIM, DIM, TT, TD, TD, 1.0f);
    }
}